// round 9
// baseline (speedup 1.0000x reference)
#include <cuda_runtime.h>
#include <math.h>

#define B_    512
#define T_    8
#define H_    512
#define K1PAD 544
#define NCTA  128
#define NTHR  128

#define BM  64
#define BN  64
#define BK  32
#define SST 36                      // 32 + 4 pad words
#define STAGES 4
#define STG_W ((BM + BN) * SST)     // words per pipeline stage (A then B)
#define SMEM_DYN (STAGES * STG_W * 4)   // 73728 bytes

// ---------------- scratch (static device globals; no allocation) ----------------
__device__ float g_a1[B_ * K1PAD];        // ODE GEMM1 input, tf32 values
__device__ float g_z1[B_ * 1024];         // tf32 values
__device__ float g_z2[B_ * 1024];         // tf32 values
__device__ float g_ks[B_ * H_];           // RK weighted sum, fp32
__device__ float g_h [B_ * H_];           // hidden state, fp32
__device__ float g_gi[B_ * T_ * 1536];    // precomputed input gates, fp32
__device__ float g_gh[B_ * 1536];         // hidden gates, fp32
__device__ float g_W1p [1024 * K1PAD];    // weights, tf32 values
__device__ float g_W2t [1024 * 1024];
__device__ float g_W3t [H_ * 1024];
__device__ float g_Whht[1536 * H_];
__device__ float g_Wiht[1536 * H_];
__device__ float g_Woutt[128 * H_];
__device__ float g_xt[B_ * T_ * H_];      // x converted to tf32
__device__ unsigned g_cnt;
__device__ volatile unsigned g_gen;

// ---------------- helpers ----------------
__device__ __forceinline__ unsigned f2tf(float f) {
    unsigned u;
    asm("cvt.rna.tf32.f32 %0, %1;" : "=r"(u) : "f"(f));
    return u;
}

__device__ __forceinline__ void mma8(float* c, const unsigned* a, const unsigned* b) {
    asm volatile(
        "mma.sync.aligned.m16n8k8.row.col.f32.tf32.tf32.f32 "
        "{%0,%1,%2,%3}, {%4,%5,%6,%7}, {%8,%9}, {%0,%1,%2,%3};"
        : "+f"(c[0]), "+f"(c[1]), "+f"(c[2]), "+f"(c[3])
        : "r"(a[0]), "r"(a[1]), "r"(a[2]), "r"(a[3]), "r"(b[0]), "r"(b[1]));
}

__device__ __forceinline__ void cpa16(unsigned d, const float* s) {
    asm volatile("cp.async.cg.shared.global [%0], [%1], 16;" :: "r"(d), "l"(s));
}
__device__ __forceinline__ void cpcommit() { asm volatile("cp.async.commit_group;"); }

// Software grid barrier; targets are relative to g_gen at kernel start so
// state carries safely across graph replays (monotonic generation counter).
// Validated in R8 — do not touch.
__device__ __forceinline__ void grid_bar(unsigned target) {
    __syncthreads();
    __threadfence();
    __syncthreads();
    if (threadIdx.x == 0) {
        unsigned a = atomicAdd(&g_cnt, 1u);
        if (a == NCTA - 1) {
            atomicExch(&g_cnt, 0u);
            __threadfence();
            g_gen = target;
        } else {
            while ((int)(g_gen - target) < 0) __nanosleep(32);
            __threadfence();
        }
    }
    __syncthreads();
}

// ---------------- GEMM phase (persistent-kernel device function) ----------------
// C-tile = A[M,K] @ Wt[N,K]^T + bias, operands already tf32 in gmem.
// 4-stage cp.async pipeline (one commit per iteration, incl. empty groups, so
// wait_group 2 always retires the chunk about to be consumed), 64x64 CTA tile,
// 4 warps of 32x32.
template<typename F>
__device__ __forceinline__ void gemm_tiles(
    const float* __restrict__ A, int lda,
    const float* __restrict__ Wt,
    const float* __restrict__ bias,
    int N, int K, int ntiles,
    const unsigned* sm, unsigned smu, F epi)
{
    const int tid  = threadIdx.x;
    const int lane = tid & 31, warp = tid >> 5;
    const int wm = warp >> 1, wn = warp & 1;
    const int g = lane >> 2, tg = lane & 3;
    const int ncol = N / BN;
    const int nch  = K / BK;

    for (int tile = blockIdx.x; tile < ntiles; tile += NCTA) {
        const int row0 = (tile / ncol) * BM;
        const int col0 = (tile % ncol) * BN;
        const float* Ab = A  + (size_t)row0 * lda;
        const float* Bb = Wt + (size_t)col0 * K;
        __syncthreads();   // previous tile's smem reads complete

        // ---- pipeline prologue: issue STAGES-1 chunks ----
        int fetch = 0;
#pragma unroll
        for (int p = 0; p < STAGES - 1; ++p) {
            if (p < nch) {
                unsigned base = smu + (unsigned)(p * STG_W) * 4u;
                int k0 = p * BK;
#pragma unroll
                for (int i = 0; i < 4; i++) {
                    int lin = tid + i * NTHR; int r = lin >> 3, c4 = (lin & 7) * 4;
                    cpa16(base + (unsigned)(r * SST + c4) * 4u,
                          Ab + (size_t)r * lda + k0 + c4);
                }
#pragma unroll
                for (int i = 0; i < 4; i++) {
                    int lin = tid + i * NTHR; int r = lin >> 3, c4 = (lin & 7) * 4;
                    cpa16(base + (unsigned)((BM + r) * SST + c4) * 4u,
                          Bb + (size_t)r * K + k0 + c4);
                }
                fetch++;
            }
            cpcommit();
        }

        float acc[2][4][4];
#pragma unroll
        for (int a = 0; a < 2; a++)
#pragma unroll
            for (int b = 0; b < 4; b++)
#pragma unroll
                for (int e = 0; e < 4; e++) acc[a][b][e] = 0.f;

        for (int ch = 0; ch < nch; ++ch) {
            // retire chunk ch (exactly 3 groups pending before this wait)
            asm volatile("cp.async.wait_group 2;" ::: "memory");
            __syncthreads();
            // issue chunk ch+3 into buffer (ch+3)&3 == (ch-1)&3: its reads
            // finished at iteration ch-1, ordered by the sync above.
            if (fetch < nch) {
                unsigned base = smu + (unsigned)((fetch & (STAGES - 1)) * STG_W) * 4u;
                int k0 = fetch * BK;
#pragma unroll
                for (int i = 0; i < 4; i++) {
                    int lin = tid + i * NTHR; int r = lin >> 3, c4 = (lin & 7) * 4;
                    cpa16(base + (unsigned)(r * SST + c4) * 4u,
                          Ab + (size_t)r * lda + k0 + c4);
                }
#pragma unroll
                for (int i = 0; i < 4; i++) {
                    int lin = tid + i * NTHR; int r = lin >> 3, c4 = (lin & 7) * 4;
                    cpa16(base + (unsigned)((BM + r) * SST + c4) * 4u,
                          Bb + (size_t)r * K + k0 + c4);
                }
                fetch++;
            }
            cpcommit();   // always commit (empty group near the tail) so the
                          // pending count stays aligned with wait_group 2

            const unsigned* a_ = sm + (ch & (STAGES - 1)) * STG_W;
            const unsigned* b_ = a_ + BM * SST;
#pragma unroll
            for (int ks = 0; ks < 4; ks++) {
                unsigned af[2][4];
#pragma unroll
                for (int mt = 0; mt < 2; mt++) {
                    int r = wm * 32 + mt * 16 + g;
                    int base = r * SST + ks * 8 + tg;
                    af[mt][0] = a_[base];
                    af[mt][1] = a_[base + 8 * SST];
                    af[mt][2] = a_[base + 4];
                    af[mt][3] = a_[base + 8 * SST + 4];
                }
#pragma unroll
                for (int nt = 0; nt < 4; nt++) {
                    int n = wn * 32 + nt * 8 + g;
                    unsigned bf[2];
                    bf[0] = b_[n * SST + ks * 8 + tg];
                    bf[1] = b_[n * SST + ks * 8 + tg + 4];
                    mma8(acc[0][nt], af[0], bf);
                    mma8(acc[1][nt], af[1], bf);
                }
            }
        }

#pragma unroll
        for (int mt = 0; mt < 2; mt++)
#pragma unroll
            for (int nt = 0; nt < 4; nt++)
#pragma unroll
                for (int e = 0; e < 4; e++) {
                    int r = row0 + wm * 32 + mt * 16 + g + ((e >= 2) ? 8 : 0);
                    int c = col0 + wn * 32 + nt * 8 + tg * 2 + (e & 1);
                    epi(r, c, acc[mt][nt][e] + bias[c]);
                }
    }
}

// ---------------- the persistent kernel ----------------
__global__ void __launch_bounds__(NTHR, 1)
ode_persist(const float* __restrict__ ts,  const float* __restrict__ bih,
            const float* __restrict__ bhh, const float* __restrict__ b1,
            const float* __restrict__ b2,  const float* __restrict__ b3,
            const float* __restrict__ bout, float* __restrict__ dout)
{
    extern __shared__ unsigned smem_dyn[];
    const unsigned smu = (unsigned)__cvta_generic_to_shared(smem_dyn);
    const unsigned* sm = smem_dyn;
    const int tid = threadIdx.x, bid = blockIdx.x;

    unsigned barn = 0, barbase = 0;
    if (tid == 0) barbase = g_gen;   // stable: cannot advance before all CTAs arrive at bar 1

    // ---- phase 0: gi = x @ Wih^T + bih (all 8 steps at once) ----
    gemm_tiles(g_xt, 512, g_Wiht, bih, 1536, 512, (4096 / BM) * (1536 / BN),
               sm, smu,
               [&](int r, int c, float v) { g_gi[(size_t)r * 1536 + c] = v; });
    barn++; grid_bar(barbase + barn);

    for (int tt = 0; tt < T_; tt++) {
        for (int s = 0; s < 4; s++) {
            for (int j = 0; j < 4; j++) {
                // G1: z1 = tf32(swish(a1 @ W1p^T + b1)),  128 tiles
                gemm_tiles(g_a1, K1PAD, g_W1p, b1, 1024, K1PAD, 128,
                           sm, smu,
                           [&](int r, int c, float v) {
                               float sw = v / (1.f + __expf(-v));
                               g_z1[(size_t)r * 1024 + c] = __uint_as_float(f2tf(sw));
                           });
                barn++; grid_bar(barbase + barn);

                // G2: z2 = tf32(swish(z1 @ W2^T + b2)),  128 tiles
                gemm_tiles(g_z1, 1024, g_W2t, b2, 1024, 1024, 128,
                           sm, smu,
                           [&](int r, int c, float v) {
                               float sw = v / (1.f + __expf(-v));
                               g_z2[(size_t)r * 1024 + c] = __uint_as_float(f2tf(sw));
                           });
                barn++; grid_bar(barbase + barn);

                // G3: k = z2 @ W3^T + b3 with fused RK accumulation AND
                // construction of the next eval's A1 = tf32(h + c_next*dt*k).
                gemm_tiles(g_z2, 1024, g_W3t, b3, H_, 1024, 64,
                           sm, smu,
                           [&](int r, int c, float v) {
                               float t1 = ts[r * T_ + tt];
                               float t0 = (tt == 0) ? ts[r * T_] : ts[r * T_ + tt - 1];
                               float dt = (t1 - t0) * 0.25f;
                               int off = r * H_ + c;
                               float a1v;
                               if (j == 0)      { g_ks[off] = v;        a1v = g_h[off] + 0.5f * dt * v; }
                               else if (j == 1) { g_ks[off] += 2.f * v; a1v = g_h[off] + 0.5f * dt * v; }
                               else if (j == 2) { g_ks[off] += 2.f * v; a1v = g_h[off] + dt * v; }
                               else {
                                   float hn = g_h[off] + dt * (1.f / 6.f) * (g_ks[off] + v);
                                   g_h[off] = hn;
                                   a1v = hn;
                               }
                               g_a1[r * K1PAD + c] = __uint_as_float(f2tf(a1v));
                           });
                // idle CTAs write the next eval's t-column
                if (bid >= 64 && bid < 68) {
                    int r = (bid - 64) * NTHR + tid;
                    float t1 = ts[r * T_ + tt];
                    float t0 = (tt == 0) ? ts[r * T_] : ts[r * T_ + tt - 1];
                    float dt = (t1 - t0) * 0.25f;
                    float sn = (j < 2) ? ((float)s + 0.5f) : ((float)s + 1.f);
                    g_a1[r * K1PAD + 512] = __uint_as_float(f2tf(t0 + sn * dt));
                }
                barn++; grid_bar(barbase + barn);
            }
        }

        // GRU: gh = h @ Whh^T + bhh  (A = a1 which holds tf32(h_ode))
        gemm_tiles(g_a1, K1PAD, g_Whht, bhh, 1536, 512, (512 / BM) * (1536 / BN),
                   sm, smu,
                   [&](int r, int c, float v) { g_gh[(size_t)r * 1536 + c] = v; });
        barn++; grid_bar(barbase + barn);

        // gate: owner-tile partition matches G3 tiles so h stays same-SM.
        // At the last step, write the h output region of dout DIRECTLY from
        // registers (validated post-timing in R7/R8).
        if (bid < 64) {
            int r0 = (bid >> 3) * 64, c0 = (bid & 7) * 64;
            for (int e = tid; e < 64 * 64; e += NTHR) {
                int r = r0 + (e >> 6), c = c0 + (e & 63);
                int off = r * H_ + c;
                size_t gio = ((size_t)(r * T_ + tt)) * 1536 + c;
                float ir  = __ldcg(&g_gi[gio]);
                float iz  = __ldcg(&g_gi[gio + 512]);
                float inn = __ldcg(&g_gi[gio + 1024]);
                size_t gho = (size_t)r * 1536 + c;
                float hr = __ldcg(&g_gh[gho]);
                float hz = __ldcg(&g_gh[gho + 512]);
                float hn = __ldcg(&g_gh[gho + 1024]);
                float hv = g_h[off];
                float rg = 1.f / (1.f + expf(-(ir + hr)));
                float zg = 1.f / (1.f + expf(-(iz + hz)));
                float ng = tanhf(inn + rg * hn);
                float h2 = (1.f - zg) * ng + zg * hv;
                g_h[off] = h2;
                g_a1[r * K1PAD + c] = __uint_as_float(f2tf(h2));
                if (tt == T_ - 1) dout[B_ * 128 + off] = h2;   // h output, direct
            }
        }
        if (bid < 4) {   // t-column for next time step: t0' = ts[:, tt]
            int r = bid * NTHR + tid;
            g_a1[r * K1PAD + 512] = __uint_as_float(f2tf(ts[r * T_ + tt]));
        }
        barn++; grid_bar(barbase + barn);
    }

    // outputs: outs[-1] = h @ Wout^T + bout (reads a1 = tf32(h_final)).
    // c output (zeros) is handled by a dedicated prologue kernel.
    gemm_tiles(g_a1, K1PAD, g_Woutt, bout, 128, 512, (512 / BM) * (128 / BN),
               sm, smu,
               [&](int r, int c, float v) { dout[(size_t)r * 128 + c] = v; });
}

// ---------------- prologue kernels ----------------
__global__ void cvt_copy(const float* __restrict__ s, float* __restrict__ d, int n) {
    int i = blockIdx.x * blockDim.x + threadIdx.x;
    if (i < n) d[i] = __uint_as_float(f2tf(s[i]));
}

__global__ void pad_w1(const float* __restrict__ W1, float* __restrict__ W1p) {
    int i = blockIdx.x * blockDim.x + threadIdx.x;
    if (i < 1024 * K1PAD) {
        int r = i / K1PAD, c = i - r * K1PAD;
        W1p[i] = (c < H_ + 1) ? __uint_as_float(f2tf(W1[r * (H_ + 1) + c])) : 0.f;
    }
}

__global__ void init_state(const float* __restrict__ ts) {
    int i = blockIdx.x * blockDim.x + threadIdx.x;
    if (i < B_ * H_) g_h[i] = 0.f;
    if (i < B_ * K1PAD) {
        int r = i / K1PAD, c = i - r * K1PAD;
        g_a1[i] = (c == 512) ? __uint_as_float(f2tf(ts[r * T_])) : 0.f;
    }
}

// c output is identically zero for every call — dedicated kernel (validated R8).
__global__ void zero_c(float* __restrict__ dout) {
    int i = blockIdx.x * blockDim.x + threadIdx.x;
    if (i < B_ * H_) dout[B_ * 128 + B_ * H_ + i] = 0.f;
}

// ---------------- driver ----------------
extern "C" void kernel_launch(void* const* d_in, const int* in_sizes, int n_in,
                              void* d_out, int out_size) {
    const float* x    = (const float*)d_in[0];
    const float* ts   = (const float*)d_in[1];
    const float* Wih  = (const float*)d_in[2];
    const float* Whh  = (const float*)d_in[3];
    const float* bih  = (const float*)d_in[4];
    const float* bhh  = (const float*)d_in[5];
    const float* Wout = (const float*)d_in[6];
    const float* bout = (const float*)d_in[7];
    const float* W1   = (const float*)d_in[8];
    const float* b1   = (const float*)d_in[9];
    const float* W2   = (const float*)d_in[10];
    const float* b2   = (const float*)d_in[11];
    const float* W3   = (const float*)d_in[12];
    const float* b3   = (const float*)d_in[13];
    float* dout = (float*)d_out;
    (void)in_sizes; (void)n_in; (void)out_size;

    float *p_xt, *p_wih, *p_whh, *p_w2, *p_w3, *p_wout, *p_w1p;
    cudaGetSymbolAddress((void**)&p_xt,   g_xt);
    cudaGetSymbolAddress((void**)&p_wih,  g_Wiht);
    cudaGetSymbolAddress((void**)&p_whh,  g_Whht);
    cudaGetSymbolAddress((void**)&p_w2,   g_W2t);
    cudaGetSymbolAddress((void**)&p_w3,   g_W3t);
    cudaGetSymbolAddress((void**)&p_wout, g_Woutt);
    cudaGetSymbolAddress((void**)&p_w1p,  g_W1p);

    cudaFuncSetAttribute(ode_persist,
                         cudaFuncAttributeMaxDynamicSharedMemorySize, SMEM_DYN);

    zero_c<<<(B_ * H_ + 255) / 256, 256>>>(dout);
    cvt_copy<<<(B_ * T_ * H_ + 255) / 256, 256>>>(x, p_xt, B_ * T_ * H_);
    cvt_copy<<<(1536 * H_ + 255) / 256, 256>>>(Wih, p_wih, 1536 * H_);
    cvt_copy<<<(1536 * H_ + 255) / 256, 256>>>(Whh, p_whh, 1536 * H_);
    cvt_copy<<<(1024 * 1024 + 255) / 256, 256>>>(W2, p_w2, 1024 * 1024);
    cvt_copy<<<(H_ * 1024 + 255) / 256, 256>>>(W3, p_w3, H_ * 1024);
    cvt_copy<<<(128 * H_ + 255) / 256, 256>>>(Wout, p_wout, 128 * H_);
    pad_w1<<<(1024 * K1PAD + 255) / 256, 256>>>(W1, p_w1p);
    init_state<<<(B_ * K1PAD + 255) / 256, 256>>>(ts);

    ode_persist<<<NCTA, NTHR, SMEM_DYN>>>(ts, bih, bhh, b1, b2, b3, bout, dout);
}

// round 10
// speedup vs baseline: 1.5717x; 1.5717x over previous
#include <cuda_runtime.h>
#include <math.h>

#define B_    512
#define T_    8
#define H_    512
#define K1PAD 544
#define NCTA  256
#define NTHR  128

#define BM  64
#define BN  32
#define BK  32
#define SST 36                      // 32 + 4 pad words
#define STAGES 3
#define STG_W ((BM + BN) * SST)     // 3456 words per stage (A then B)

// ---------------- scratch (static device globals; no allocation) ----------------
__device__ float g_a1[B_ * K1PAD];        // ODE GEMM1 input, tf32 values
__device__ float g_z1[B_ * 1024];         // tf32 values
__device__ float g_z2[B_ * 1024];         // tf32 values
__device__ float g_ks[B_ * H_];           // RK weighted sum, fp32
__device__ float g_h [B_ * H_];           // hidden state, fp32
__device__ float g_gi[B_ * T_ * 1536];    // precomputed input gates, fp32
__device__ float g_gh[B_ * 1536];         // hidden gates, fp32
__device__ float g_W1p [1024 * K1PAD];    // weights, tf32 values
__device__ float g_W2t [1024 * 1024];
__device__ float g_W3t [H_ * 1024];
__device__ float g_Whht[1536 * H_];
__device__ float g_Wiht[1536 * H_];
__device__ float g_Woutt[128 * H_];
__device__ float g_xt[B_ * T_ * H_];      // x converted to tf32
__device__ unsigned g_cnt;
__device__ volatile unsigned g_gen;

// ---------------- helpers ----------------
__device__ __forceinline__ unsigned f2tf(float f) {
    unsigned u;
    asm("cvt.rna.tf32.f32 %0, %1;" : "=r"(u) : "f"(f));
    return u;
}

__device__ __forceinline__ void mma8(float* c, const unsigned* a, const unsigned* b) {
    asm volatile(
        "mma.sync.aligned.m16n8k8.row.col.f32.tf32.tf32.f32 "
        "{%0,%1,%2,%3}, {%4,%5,%6,%7}, {%8,%9}, {%0,%1,%2,%3};"
        : "+f"(c[0]), "+f"(c[1]), "+f"(c[2]), "+f"(c[3])
        : "r"(a[0]), "r"(a[1]), "r"(a[2]), "r"(a[3]), "r"(b[0]), "r"(b[1]));
}

__device__ __forceinline__ void cpa16(unsigned d, const float* s) {
    asm volatile("cp.async.cg.shared.global [%0], [%1], 16;" :: "r"(d), "l"(s));
}
__device__ __forceinline__ void cpcommit() { asm volatile("cp.async.commit_group;"); }

// Software grid barrier; targets are relative to g_gen at kernel start so
// state carries safely across graph replays (monotonic generation counter).
// Validated in R8 — structure unchanged (count updated to NCTA=256).
__device__ __forceinline__ void grid_bar(unsigned target) {
    __syncthreads();
    __threadfence();
    __syncthreads();
    if (threadIdx.x == 0) {
        unsigned a = atomicAdd(&g_cnt, 1u);
        if (a == NCTA - 1) {
            atomicExch(&g_cnt, 0u);
            __threadfence();
            g_gen = target;
        } else {
            while ((int)(g_gen - target) < 0) __nanosleep(32);
            __threadfence();
        }
    }
    __syncthreads();
}

// ---------------- GEMM phase (persistent-kernel device function) ----------------
// C-tile = A[M,K] @ Wt[N,K]^T + bias, operands already tf32 in gmem.
// 64x32 CTA tile, 4 warps each 16x32. 3-stage static-smem cp.async pipeline:
// at iteration ch we retire chunk ch (wait_group 1 keeps ch+1 in flight),
// issue ch+2, then compute ch — each load gets ~2 compute phases of cover.
template<typename F>
__device__ __forceinline__ void gemm_tiles(
    const float* __restrict__ A, int lda,
    const float* __restrict__ Wt,
    const float* __restrict__ bias,
    int N, int K, int ntiles,
    const unsigned* sm, unsigned smu, F epi)
{
    const int tid  = threadIdx.x;
    const int lane = tid & 31, warp = tid >> 5;
    const int g = lane >> 2, tg = lane & 3;
    const int ncol = N / BN;
    const int nch  = K / BK;

    for (int tile = blockIdx.x; tile < ntiles; tile += NCTA) {
        const int row0 = (tile / ncol) * BM;
        const int col0 = (tile % ncol) * BN;
        const float* Ab = A  + (size_t)row0 * lda;
        const float* Bb = Wt + (size_t)col0 * K;
        __syncthreads();   // previous tile's smem reads complete

        auto issue = [&](int ck, int st) {
            unsigned base = smu + (unsigned)(st * STG_W) * 4u;
            int k0 = ck * BK;
#pragma unroll
            for (int i = 0; i < 4; i++) {   // A: 64x32 = 512 float4, 4/thread
                int lin = tid + i * NTHR; int r = lin >> 3, c4 = (lin & 7) * 4;
                cpa16(base + (unsigned)(r * SST + c4) * 4u,
                      Ab + (size_t)r * lda + k0 + c4);
            }
#pragma unroll
            for (int i = 0; i < 2; i++) {   // B: 32x32 = 256 float4, 2/thread
                int lin = tid + i * NTHR; int r = lin >> 3, c4 = (lin & 7) * 4;
                cpa16(base + (unsigned)((BM + r) * SST + c4) * 4u,
                      Bb + (size_t)r * K + k0 + c4);
            }
        };

        // pipeline prologue: chunks 0 and 1 (always 2 commits)
        issue(0, 0); cpcommit();
        if (nch > 1) issue(1, 1);
        cpcommit();

        float acc[4][4];
#pragma unroll
        for (int b = 0; b < 4; b++)
#pragma unroll
            for (int e = 0; e < 4; e++) acc[b][e] = 0.f;

        for (int ch = 0; ch < nch; ++ch) {
            // retire chunk ch; keep ch+1 in flight
            asm volatile("cp.async.wait_group 1;" ::: "memory");
            __syncthreads();
            // issue ch+2 into buffer (ch+2)%3 == (ch-1)%3, whose reads
            // completed at iteration ch-1 (ordered by the sync above)
            if (ch + 2 < nch) issue(ch + 2, (ch + 2) % STAGES);
            cpcommit();     // always commit so pending count stays aligned

            const unsigned* a_ = sm + (ch % STAGES) * STG_W;
            const unsigned* b_ = a_ + BM * SST;
#pragma unroll
            for (int ks = 0; ks < 4; ks++) {
                unsigned af[4];
                {
                    int r = warp * 16 + g;
                    int base = r * SST + ks * 8 + tg;
                    af[0] = a_[base];
                    af[1] = a_[base + 8 * SST];
                    af[2] = a_[base + 4];
                    af[3] = a_[base + 8 * SST + 4];
                }
#pragma unroll
                for (int nt = 0; nt < 4; nt++) {
                    int n = nt * 8 + g;
                    unsigned bf[2];
                    bf[0] = b_[n * SST + ks * 8 + tg];
                    bf[1] = b_[n * SST + ks * 8 + tg + 4];
                    mma8(acc[nt], af, bf);
                }
            }
        }

#pragma unroll
        for (int nt = 0; nt < 4; nt++)
#pragma unroll
            for (int e = 0; e < 4; e++) {
                int r = row0 + warp * 16 + g + ((e >= 2) ? 8 : 0);
                int c = col0 + nt * 8 + tg * 2 + (e & 1);
                epi(r, c, acc[nt][e] + bias[c]);
            }
    }
}

// ---------------- the persistent kernel ----------------
__global__ void __launch_bounds__(NTHR, 2)
ode_persist(const float* __restrict__ ts,  const float* __restrict__ bih,
            const float* __restrict__ bhh, const float* __restrict__ b1,
            const float* __restrict__ b2,  const float* __restrict__ b3,
            const float* __restrict__ bout, float* __restrict__ dout)
{
    __shared__ unsigned smem[STAGES * STG_W];     // 41472 bytes
    const unsigned smu = (unsigned)__cvta_generic_to_shared(smem);
    const unsigned* sm = smem;
    const int tid = threadIdx.x, bid = blockIdx.x;

    unsigned barn = 0, barbase = 0;
    if (tid == 0) barbase = g_gen;   // stable: cannot advance before all CTAs arrive at bar 1

    // ---- phase 0: gi = x @ Wih^T + bih (all 8 steps at once) ----
    gemm_tiles(g_xt, 512, g_Wiht, bih, 1536, 512, (4096 / BM) * (1536 / BN),
               sm, smu,
               [&](int r, int c, float v) { g_gi[(size_t)r * 1536 + c] = v; });
    barn++; grid_bar(barbase + barn);

    for (int tt = 0; tt < T_; tt++) {
        for (int s = 0; s < 4; s++) {
            for (int j = 0; j < 4; j++) {
                // G1: z1 = tf32(swish(a1 @ W1p^T + b1)),  256 tiles
                gemm_tiles(g_a1, K1PAD, g_W1p, b1, 1024, K1PAD, 256,
                           sm, smu,
                           [&](int r, int c, float v) {
                               float sw = v / (1.f + __expf(-v));
                               g_z1[(size_t)r * 1024 + c] = __uint_as_float(f2tf(sw));
                           });
                barn++; grid_bar(barbase + barn);

                // G2: z2 = tf32(swish(z1 @ W2^T + b2)),  256 tiles
                gemm_tiles(g_z1, 1024, g_W2t, b2, 1024, 1024, 256,
                           sm, smu,
                           [&](int r, int c, float v) {
                               float sw = v / (1.f + __expf(-v));
                               g_z2[(size_t)r * 1024 + c] = __uint_as_float(f2tf(sw));
                           });
                barn++; grid_bar(barbase + barn);

                // G3: k = z2 @ W3^T + b3 with fused RK accumulation AND
                // construction of the next eval's A1 = tf32(h + c_next*dt*k).
                // 128 tiles: CTAs 0..127 own fixed (64x32) blocks of h/ks.
                gemm_tiles(g_z2, 1024, g_W3t, b3, H_, 1024, 128,
                           sm, smu,
                           [&](int r, int c, float v) {
                               float t1 = ts[r * T_ + tt];
                               float t0 = (tt == 0) ? ts[r * T_] : ts[r * T_ + tt - 1];
                               float dt = (t1 - t0) * 0.25f;
                               int off = r * H_ + c;
                               float a1v;
                               if (j == 0)      { g_ks[off] = v;        a1v = g_h[off] + 0.5f * dt * v; }
                               else if (j == 1) { g_ks[off] += 2.f * v; a1v = g_h[off] + 0.5f * dt * v; }
                               else if (j == 2) { g_ks[off] += 2.f * v; a1v = g_h[off] + dt * v; }
                               else {
                                   float hn = g_h[off] + dt * (1.f / 6.f) * (g_ks[off] + v);
                                   g_h[off] = hn;
                                   a1v = hn;
                               }
                               g_a1[r * K1PAD + c] = __uint_as_float(f2tf(a1v));
                           });
                // idle CTAs write the next eval's t-column
                if (bid >= 128 && bid < 132) {
                    int r = (bid - 128) * NTHR + tid;
                    float t1 = ts[r * T_ + tt];
                    float t0 = (tt == 0) ? ts[r * T_] : ts[r * T_ + tt - 1];
                    float dt = (t1 - t0) * 0.25f;
                    float sn = (j < 2) ? ((float)s + 0.5f) : ((float)s + 1.f);
                    g_a1[r * K1PAD + 512] = __uint_as_float(f2tf(t0 + sn * dt));
                }
                barn++; grid_bar(barbase + barn);
            }
        }

        // GRU: gh = h @ Whh^T + bhh  (A = a1 which holds tf32(h_ode))
        gemm_tiles(g_a1, K1PAD, g_Whht, bhh, 1536, 512, (512 / BM) * (1536 / BN),
                   sm, smu,
                   [&](int r, int c, float v) { g_gh[(size_t)r * 1536 + c] = v; });
        barn++; grid_bar(barbase + barn);

        // gate: partition matches G3 tile ownership (bid<128 → 64x32 block)
        // so g_h stays CTA-local. At the last step, write the h output
        // region of dout DIRECTLY from registers (validated in R7/R8).
        if (bid < 128) {
            int r0 = (bid >> 4) * 64, c0 = (bid & 15) * 32;
            for (int e = tid; e < 64 * 32; e += NTHR) {
                int r = r0 + (e >> 5), c = c0 + (e & 31);
                int off = r * H_ + c;
                size_t gio = ((size_t)(r * T_ + tt)) * 1536 + c;
                float ir  = __ldcg(&g_gi[gio]);
                float iz  = __ldcg(&g_gi[gio + 512]);
                float inn = __ldcg(&g_gi[gio + 1024]);
                size_t gho = (size_t)r * 1536 + c;
                float hr = __ldcg(&g_gh[gho]);
                float hz = __ldcg(&g_gh[gho + 512]);
                float hn = __ldcg(&g_gh[gho + 1024]);
                float hv = g_h[off];
                float rg = 1.f / (1.f + expf(-(ir + hr)));
                float zg = 1.f / (1.f + expf(-(iz + hz)));
                float ng = tanhf(inn + rg * hn);
                float h2 = (1.f - zg) * ng + zg * hv;
                g_h[off] = h2;
                g_a1[r * K1PAD + c] = __uint_as_float(f2tf(h2));
                if (tt == T_ - 1) dout[B_ * 128 + off] = h2;   // h output, direct
            }
        }
        if (bid >= 128 && bid < 132) {   // t-column for next time step
            int r = (bid - 128) * NTHR + tid;
            g_a1[r * K1PAD + 512] = __uint_as_float(f2tf(ts[r * T_ + tt]));
        }
        barn++; grid_bar(barbase + barn);
    }

    // outputs: outs[-1] = h @ Wout^T + bout (reads a1 = tf32(h_final)).
    // c output (zeros) is handled by a dedicated prologue kernel.
    gemm_tiles(g_a1, K1PAD, g_Woutt, bout, 128, 512, (512 / BM) * (128 / BN),
               sm, smu,
               [&](int r, int c, float v) { dout[(size_t)r * 128 + c] = v; });
}

// ---------------- prologue kernels (exactly 5 launches before ode_persist,
// so ncu's "-s 5 -c 1" captures the persistent kernel) ----------------
__global__ void zero_c(float* __restrict__ dout) {
    int i = blockIdx.x * blockDim.x + threadIdx.x;
    if (i < B_ * H_) dout[B_ * 128 + B_ * H_ + i] = 0.f;
}

__global__ void cvt_many(const float* __restrict__ s0, float* __restrict__ d0, int n0,
                         const float* __restrict__ s1, float* __restrict__ d1, int n1,
                         const float* __restrict__ s2, float* __restrict__ d2, int n2) {
    int i = blockIdx.x * blockDim.x + threadIdx.x;
    if (i < n0) d0[i] = __uint_as_float(f2tf(s0[i]));
    if (i < n1) d1[i] = __uint_as_float(f2tf(s1[i]));
    if (i < n2) d2[i] = __uint_as_float(f2tf(s2[i]));
}

__global__ void pad_w1(const float* __restrict__ W1, float* __restrict__ W1p) {
    int i = blockIdx.x * blockDim.x + threadIdx.x;
    if (i < 1024 * K1PAD) {
        int r = i / K1PAD, c = i - r * K1PAD;
        W1p[i] = (c < H_ + 1) ? __uint_as_float(f2tf(W1[r * (H_ + 1) + c])) : 0.f;
    }
}

__global__ void init_state(const float* __restrict__ ts) {
    int i = blockIdx.x * blockDim.x + threadIdx.x;
    if (i < B_ * H_) g_h[i] = 0.f;
    if (i < B_ * K1PAD) {
        int r = i / K1PAD, c = i - r * K1PAD;
        g_a1[i] = (c == 512) ? __uint_as_float(f2tf(ts[r * T_])) : 0.f;
    }
}

// ---------------- driver ----------------
extern "C" void kernel_launch(void* const* d_in, const int* in_sizes, int n_in,
                              void* d_out, int out_size) {
    const float* x    = (const float*)d_in[0];
    const float* ts   = (const float*)d_in[1];
    const float* Wih  = (const float*)d_in[2];
    const float* Whh  = (const float*)d_in[3];
    const float* bih  = (const float*)d_in[4];
    const float* bhh  = (const float*)d_in[5];
    const float* Wout = (const float*)d_in[6];
    const float* bout = (const float*)d_in[7];
    const float* W1   = (const float*)d_in[8];
    const float* b1   = (const float*)d_in[9];
    const float* W2   = (const float*)d_in[10];
    const float* b2   = (const float*)d_in[11];
    const float* W3   = (const float*)d_in[12];
    const float* b3   = (const float*)d_in[13];
    float* dout = (float*)d_out;
    (void)in_sizes; (void)n_in; (void)out_size;

    float *p_xt, *p_wih, *p_whh, *p_w2, *p_w3, *p_wout, *p_w1p;
    cudaGetSymbolAddress((void**)&p_xt,   g_xt);
    cudaGetSymbolAddress((void**)&p_wih,  g_Wiht);
    cudaGetSymbolAddress((void**)&p_whh,  g_Whht);
    cudaGetSymbolAddress((void**)&p_w2,   g_W2t);
    cudaGetSymbolAddress((void**)&p_w3,   g_W3t);
    cudaGetSymbolAddress((void**)&p_wout, g_Woutt);
    cudaGetSymbolAddress((void**)&p_w1p,  g_W1p);

    cudaFuncSetAttribute(ode_persist,
                         cudaFuncAttributePreferredSharedMemoryCarveout, 100);

    // exactly 5 launches before ode_persist (ncu -s 5 -c 1 → captures it)
    zero_c<<<(B_ * H_ + 255) / 256, 256>>>(dout);
    cvt_many<<<(B_ * T_ * H_ + 255) / 256, 256>>>(
        x, p_xt, B_ * T_ * H_, Wih, p_wih, 1536 * H_, Whh, p_whh, 1536 * H_);
    cvt_many<<<(1024 * 1024 + 255) / 256, 256>>>(
        W2, p_w2, 1024 * 1024, W3, p_w3, H_ * 1024, Wout, p_wout, 128 * H_);
    pad_w1<<<(1024 * K1PAD + 255) / 256, 256>>>(W1, p_w1p);
    init_state<<<(B_ * K1PAD + 255) / 256, 256>>>(ts);

    ode_persist<<<NCTA, NTHR>>>(ts, bih, bhh, b1, b2, b3, bout, dout);
}